// round 6
// baseline (speedup 1.0000x reference)
#include <cuda_runtime.h>
#include <cstddef>

// DCTFeatureModel — collapsed linear model:
// feat[b,s,o] = sum_{t,ij} xc[b,s,t,ij] * Veff[s,o,t,ij] + bias[s,o]
//   xc[b,s,t,ij]    = sum_c x[b, s*256 + c*32 + t, ij]
//   Veff[s,o,t,i,j] = (1/8) sum_{f,p,q} Ct[f,t] Cs[p,i] Cs[q,j] W[s,o,f,p,q]
// out[b, s*64+o] = leaky_relu(feat)
//
// kernel 1: prep  (Veff transform, 256 CTAs)
// kernel 2: main  (16-phase software-pipelined GEMM + fused epilogue)

#define NSW 2
#define NF 64
#define KSPLIT 16
#define GRID 512

__device__ __align__(16) float g_veff[NSW * 32 * 64 * 64];        // [s][t][ij][o], 1 MB
__device__ __align__(16) float g_part[KSPLIT * 1024 * NSW * NF];  // 8 MB
__device__ int g_grp[32];   // per-(s,mt) arrival counters (self-reset each launch)
__device__ int g_done;      // reducer counter (self-reset)

typedef unsigned long long u64;

__device__ __forceinline__ u64 pk2(float a, float b) {
    u64 r; asm("mov.b64 %0,{%1,%2};" : "=l"(r) : "f"(a), "f"(b)); return r;
}
__device__ __forceinline__ float2 up2(u64 a) {
    float2 v; asm("mov.b64 {%0,%1},%2;" : "=f"(v.x), "=f"(v.y) : "l"(a)); return v;
}
__device__ __forceinline__ void fma2(u64& d, u64 a, u64 b) {
    asm("fma.rn.f32x2 %0,%1,%2,%0;" : "+l"(d) : "l"(a), "l"(b));
}
__device__ __forceinline__ u64 add2(u64 a, u64 b) {
    u64 r; asm("add.rn.f32x2 %0,%1,%2;" : "=l"(r) : "l"(a), "l"(b)); return r;
}

// ---------------------------------------------------------------------------
// prep: one CTA per (s, o, t-half) -> 256 CTAs, all 256 threads in each stage.
// ---------------------------------------------------------------------------
__global__ void __launch_bounds__(256) prep_kernel(const float* __restrict__ W) {
    __shared__ __align__(16) float A[2048];   // W[s,o][f][pq]
    __shared__ __align__(16) float Bf[1024];  // [tl][p*8+q], tl<16
    __shared__ __align__(16) float B2[1024];  // [tl][i*8+q]
    __shared__ __align__(16) float Ct[512];   // [tl][f]
    __shared__ __align__(16) float Cs[64];    // [i][p]
    __shared__ __align__(16) float Cst[64];   // [q][j]

    const int tid = threadIdx.x;
    const int bx = blockIdx.x;       // s*128 + o*2 + th
    const int th = bx & 1;
    const int o = (bx >> 1) & 63;
    const int s = bx >> 7;

    // tables
#pragma unroll
    for (int r = 0; r < 2; ++r) {
        int idx = tid + 256 * r;
        int tl = idx >> 5, f = idx & 31;
        Ct[idx] = 2.0f * cospif((float)((2 * (th * 16 + tl) + 1) * f) / 64.0f);
    }
    if (tid < 64) {
        int i = tid >> 3, p = tid & 7;
        Cs[tid] = 2.0f * cospif((float)((2 * i + 1) * p) / 16.0f);
    } else if (tid < 128) {
        int e = tid - 64, q = e >> 3, j = e & 7;
        Cst[e] = 2.0f * cospif((float)((2 * j + 1) * q) / 16.0f);
    }
    {
        const float4* Wso = (const float4*)(W + ((size_t)(s * 64 + o) << 11));
        ((float4*)A)[tid] = Wso[tid];
        ((float4*)A)[tid + 256] = Wso[tid + 256];
    }
    __syncthreads();

    const int tl = tid >> 4;

    // stage 1: f -> t.  task (tl, g): 16x16 = 256
    {
        int g = tid & 15;
        u64 a01 = 0, a23 = 0;
#pragma unroll
        for (int f = 0; f < 32; ++f) {
            float4 av = ((const float4*)A)[f * 16 + g];
            float c = Ct[tl * 32 + f];
            u64 cc = pk2(c, c);
            fma2(a01, pk2(av.x, av.y), cc);
            fma2(a23, pk2(av.z, av.w), cc);
        }
        float2 v0 = up2(a01), v1 = up2(a23);
        *(float4*)&Bf[tl * 64 + 4 * g] = make_float4(v0.x, v0.y, v1.x, v1.y);
    }
    __syncthreads();

    const int i8 = (tid >> 1) & 7;
    const int hg = tid & 1;

    // stage 2: p -> i.  task (tl, i, qg): 16x8x2 = 256
    {
        u64 a01 = 0, a23 = 0;
#pragma unroll
        for (int p = 0; p < 8; ++p) {
            float4 bv = *(const float4*)&Bf[tl * 64 + p * 8 + 4 * hg];
            float c = Cs[i8 * 8 + p];
            u64 cc = pk2(c, c);
            fma2(a01, pk2(bv.x, bv.y), cc);
            fma2(a23, pk2(bv.z, bv.w), cc);
        }
        float2 v0 = up2(a01), v1 = up2(a23);
        *(float4*)&B2[tl * 64 + i8 * 8 + 4 * hg] = make_float4(v0.x, v0.y, v1.x, v1.y);
    }
    __syncthreads();

    // stage 3: q -> j, scale, scatter.  task (tl, i, jg): 256
    {
        float4 ba = *(const float4*)&B2[tl * 64 + i8 * 8];
        float4 bb = *(const float4*)&B2[tl * 64 + i8 * 8 + 4];
        float bq[8] = {ba.x, ba.y, ba.z, ba.w, bb.x, bb.y, bb.z, bb.w};
        u64 a01 = 0, a23 = 0;
#pragma unroll
        for (int q = 0; q < 8; ++q) {
            float4 cj = *(const float4*)&Cst[q * 8 + 4 * hg];
            u64 bp = pk2(bq[q], bq[q]);
            fma2(a01, bp, pk2(cj.x, cj.y));
            fma2(a23, bp, pk2(cj.z, cj.w));
        }
        int t = th * 16 + tl;
        float* base = g_veff + (((size_t)(s * 32 + t) << 6) + i8 * 8 + 4 * hg) * 64 + o;
        float2 v0 = up2(a01), v1 = up2(a23);
        base[0] = 0.125f * v0.x;
        base[64] = 0.125f * v0.y;
        base[128] = 0.125f * v1.x;
        base[192] = 0.125f * v1.y;
    }
}

// ---------------------------------------------------------------------------
// main: 512 CTAs x 256 thr, occ 4 (single wave). 16 phases of 8 k.
// Invariant at phase-p entry: smem buf(p&1) = data(p); xr/wsrc = data(p+1).
// Body: STS data(p+1) -> other buf (no stall), issue LDG data(p+2),
//       COMP from buf(p), barrier.  Full-phase load->use distance.
// Fused epilogue: last CTA per (s,mt) group reduces 16 partials.
// ---------------------------------------------------------------------------
__global__ void __launch_bounds__(256, 4) main_kernel(
    const float* __restrict__ x, const float* __restrict__ bias,
    float* __restrict__ out) {
    __shared__ __align__(16) float xs[2][8][68];    // [buf][ij_local][b]
    __shared__ __align__(16) float2 wd[2][8][64];   // [buf][ij_local][o] dup pairs
    __shared__ int s_win;

    const int tid = threadIdx.x;
    const int bx = blockIdx.x;
    const int ks = bx & 15;
    const int mt = (bx >> 4) & 15;
    const int s = bx >> 8;

    const int ijp = tid & 3, bL = tid >> 2;   // load map: ij = 2*ijp(+1), b = bL
    const int tx = tid & 15, ty = tid >> 4;   // compute map: o = 4tx.., b = 4ty..

    // x[b][time][ij]; t base = ks*2 -> +ks*128 floats
    const float* xb = x + (size_t)(mt * 64 + bL) * 32768 + (size_t)s * 16384
                        + (size_t)ks * 128 + 2 * ijp;
    const float2* wg = (const float2*)(g_veff + ((size_t)s * 32 + ks * 2) * 4096);

    u64 acc[2][4] = {};
    u64 xr[8];
    float2 wsrc;

    // phase ph: t = ks*2 + (ph>>3), ij0 = (ph&7)*8
#define XOFF(ph) (((ph) >> 3) * 64 + ((ph) & 7) * 8)

#define LDG_U(ph)                                                             \
    do {                                                                      \
        const u64* p = (const u64*)(xb + XOFF(ph));                           \
        _Pragma("unroll") for (int c = 0; c < 8; ++c) xr[c] = p[c * 1024];    \
    } while (0)

#define LDG_W(ph) do { wsrc = wg[XOFF(ph) * 32 + tid]; } while (0)

#define STS_U(buf)                                                            \
    do {                                                                      \
        u64 s0 = add2(add2(xr[0], xr[1]), add2(xr[2], xr[3]));                \
        u64 s1 = add2(add2(xr[4], xr[5]), add2(xr[6], xr[7]));                \
        float2 v = up2(add2(s0, s1));                                         \
        xs[buf][2 * ijp][bL] = v.x;                                           \
        xs[buf][2 * ijp + 1][bL] = v.y;                                       \
    } while (0)

#define STS_W(buf)                                                            \
    do {                                                                      \
        ((float4*)&wd[buf][0][0])[tid] =                                      \
            make_float4(wsrc.x, wsrc.x, wsrc.y, wsrc.y);                      \
    } while (0)

#define COMP8(buf)                                                            \
    do {                                                                      \
        _Pragma("unroll") for (int k = 0; k < 8; ++k) {                       \
            ulonglong2 xp = *(const ulonglong2*)&xs[buf][k][4 * ty];          \
            ulonglong2 wA = *(const ulonglong2*)&wd[buf][k][4 * tx];          \
            ulonglong2 wB = *(const ulonglong2*)&wd[buf][k][4 * tx + 2];      \
            fma2(acc[0][0], xp.x, wA.x); fma2(acc[1][0], xp.y, wA.x);         \
            fma2(acc[0][1], xp.x, wA.y); fma2(acc[1][1], xp.y, wA.y);         \
            fma2(acc[0][2], xp.x, wB.x); fma2(acc[1][2], xp.y, wB.x);         \
            fma2(acc[0][3], xp.x, wB.y); fma2(acc[1][3], xp.y, wB.y);         \
        }                                                                     \
    } while (0)

    // prologue: buf0 = data(0); regs = data(1)
    LDG_U(0); LDG_W(0);
    STS_U(0); STS_W(0);
    LDG_U(1); LDG_W(1);
    __syncthreads();

#pragma unroll
    for (int ph = 0; ph < 16; ++ph) {
        const int buf = ph & 1, nb = buf ^ 1;
        if (ph < 15) { STS_U(nb); STS_W(nb); }
        if (ph < 14) { LDG_U(ph + 2); LDG_W(ph + 2); }
        COMP8(buf);
        if (ph < 15) __syncthreads();
    }

    // write partials: g_part[ks][b][s*64+o]
    {
        const int b0 = mt * 64 + 4 * ty;
        const int obase = s * 64 + 4 * tx;
#pragma unroll
        for (int p = 0; p < 2; ++p) {
            float2 c0 = up2(acc[p][0]), c1 = up2(acc[p][1]);
            float2 c2 = up2(acc[p][2]), c3 = up2(acc[p][3]);
            float4 r0 = make_float4(c0.x, c1.x, c2.x, c3.x);
            float4 r1 = make_float4(c0.y, c1.y, c2.y, c3.y);
            *(float4*)(g_part + ((size_t)ks << 17) + (size_t)(b0 + 2 * p) * 128 + obase) = r0;
            *(float4*)(g_part + ((size_t)ks << 17) + (size_t)(b0 + 2 * p + 1) * 128 + obase) = r1;
        }
    }

    // fused epilogue: last CTA of each (s,mt) group reduces its 64b x 64o block
    __threadfence();
    __syncthreads();
    if (tid == 0) {
        int old = atomicAdd(&g_grp[bx >> 4], 1);
        s_win = (old == 15);
        if (old == 15) g_grp[bx >> 4] = 0;  // self-reset for next replay
    }
    __syncthreads();

    if (s_win) {
        __threadfence();
#pragma unroll
        for (int u = 0; u < 4; ++u) {
            int v = tid + 256 * u;
            int bl = v >> 4, so4 = v & 15;
            size_t off = (size_t)(mt * 64 + bl) * 128 + s * 64 + so4 * 4;
            float4 bv = *(const float4*)(bias + s * 64 + so4 * 4);
            u64 a0 = pk2(bv.x, bv.y), a1 = pk2(bv.z, bv.w);
#pragma unroll
            for (int k = 0; k < KSPLIT; ++k) {
                ulonglong2 pp = *(const ulonglong2*)(g_part + ((size_t)k << 17) + off);
                a0 = add2(a0, pp.x);
                a1 = add2(a1, pp.y);
            }
            float2 f0 = up2(a0), f1 = up2(a1);
            float4 r;
            r.x = (f0.x >= 0.0f) ? f0.x : 0.02f * f0.x;
            r.y = (f0.y >= 0.0f) ? f0.y : 0.02f * f0.y;
            r.z = (f1.x >= 0.0f) ? f1.x : 0.02f * f1.x;
            r.w = (f1.y >= 0.0f) ? f1.y : 0.02f * f1.y;
            *(float4*)(out + off) = r;
        }
        if (tid == 0) {
            int d = atomicAdd(&g_done, 1);
            if (d == 31) g_done = 0;  // self-reset
        }
    }
}

// ---------------------------------------------------------------------------
extern "C" void kernel_launch(void* const* d_in, const int* in_sizes, int n_in,
                              void* d_out, int out_size) {
    const float* x = nullptr;
    const float* W = nullptr;
    const float* bias = nullptr;
    for (int i = 0; i < n_in; ++i) {
        if (in_sizes[i] == 1024 * 512 * 64) x = (const float*)d_in[i];
        else if (in_sizes[i] == NSW * NF * 32 * 64) W = (const float*)d_in[i];
        else if (in_sizes[i] == NSW * NF) bias = (const float*)d_in[i];
    }
    if (!x) x = (const float*)d_in[0];
    if (!W) W = (const float*)d_in[1];
    if (!bias) bias = (const float*)d_in[2];

    prep_kernel<<<NSW * NF * 2, 256>>>(W);
    main_kernel<<<GRID, 256>>>(x, bias, (float*)d_out);
}